// round 7
// baseline (speedup 1.0000x reference)
#include <cuda_runtime.h>
#include <cuda_bf16.h>

// Problem constants
#define BATCH 4
#define SEQ   2048
#define EMBD  1024
#define NHEAD 16
#define HDIM  64
#define QKV_N (3*EMBD)

typedef __nv_bfloat16 bf16;

// ---------------------------------------------------------------------------
// Scratch (device globals: allocation-free, graph-capture safe)
// ---------------------------------------------------------------------------
__device__ __align__(256) bf16 g_xh[(size_t)BATCH * SEQ * EMBD];
__device__ __align__(256) bf16 g_xl[(size_t)BATCH * SEQ * EMBD];
__device__ __align__(256) bf16 g_wqh[(size_t)EMBD * QKV_N];
__device__ __align__(256) bf16 g_wql[(size_t)EMBD * QKV_N];
__device__ __align__(256) bf16 g_woh[(size_t)EMBD * EMBD];
__device__ __align__(256) bf16 g_wol[(size_t)EMBD * EMBD];
__device__ __align__(256) bf16 g_qkvh[(size_t)BATCH * SEQ * QKV_N];
__device__ __align__(256) bf16 g_qkvl[(size_t)BATCH * SEQ * QKV_N];
__device__ __align__(256) bf16 g_ah[(size_t)BATCH * SEQ * EMBD];
__device__ __align__(256) bf16 g_al[(size_t)BATCH * SEQ * EMBD];

// ---------------------------------------------------------------------------
// Common PTX helpers
// ---------------------------------------------------------------------------
__device__ __forceinline__ unsigned sptr(const void* p) {
    return (unsigned)__cvta_generic_to_shared(p);
}
__device__ __forceinline__ void cpa16(unsigned s, const void* g) {
    asm volatile("cp.async.cg.shared.global [%0], [%1], 16;\n" :: "r"(s), "l"(g));
}
__device__ __forceinline__ void ldsm4(unsigned* r, unsigned a) {
    asm volatile("ldmatrix.sync.aligned.m8n8.x4.shared.b16 {%0,%1,%2,%3},[%4];"
                 : "=r"(r[0]), "=r"(r[1]), "=r"(r[2]), "=r"(r[3]) : "r"(a));
}
__device__ __forceinline__ void ldsm4t(unsigned* r, unsigned a) {
    asm volatile("ldmatrix.sync.aligned.m8n8.x4.trans.shared.b16 {%0,%1,%2,%3},[%4];"
                 : "=r"(r[0]), "=r"(r[1]), "=r"(r[2]), "=r"(r[3]) : "r"(a));
}
__device__ __forceinline__ void mma16816(float* d, const unsigned* a, const unsigned* b) {
    asm volatile(
        "mma.sync.aligned.m16n8k16.row.col.f32.bf16.bf16.f32 "
        "{%0,%1,%2,%3},{%4,%5,%6,%7},{%8,%9},{%0,%1,%2,%3};"
        : "+f"(d[0]), "+f"(d[1]), "+f"(d[2]), "+f"(d[3])
        : "r"(a[0]), "r"(a[1]), "r"(a[2]), "r"(a[3]), "r"(b[0]), "r"(b[1]));
}
// split fp32 pair -> packed bf16x2 hi + lo
__device__ __forceinline__ void split2(float a, float b, unsigned& h, unsigned& l) {
    bf16 ah = __float2bfloat16_rn(a);
    bf16 bh = __float2bfloat16_rn(b);
    bf16 al = __float2bfloat16_rn(a - __bfloat162float(ah));
    bf16 bl = __float2bfloat16_rn(b - __bfloat162float(bh));
    h = (unsigned)__bfloat16_as_ushort(ah) | ((unsigned)__bfloat16_as_ushort(bh) << 16);
    l = (unsigned)__bfloat16_as_ushort(al) | ((unsigned)__bfloat16_as_ushort(bl) << 16);
}

// ---------------------------------------------------------------------------
// fp32 -> (bf16 hi, bf16 lo) split, vectorized x4
// ---------------------------------------------------------------------------
__global__ __launch_bounds__(256) void split_bf16x4(
    const float4* __restrict__ in, uint2* __restrict__ hi, uint2* __restrict__ lo, int n4)
{
    int i = blockIdx.x * blockDim.x + threadIdx.x;
    if (i >= n4) return;
    float4 v = in[i];
    uint2 ho, loo;
    split2(v.x, v.y, ho.x, loo.x);
    split2(v.z, v.w, ho.y, loo.y);
    hi[i] = ho;
    lo[i] = loo;
}

// ---------------------------------------------------------------------------
// Tensor-core GEMM, bf16x3 emulated fp32: C = Ah@Bh + Ah@Bl + Al@Bh + bias
// MMAs issued in 3 passes (hh, hl, lh) -> accumulator reuse distance 16.
// OMODE 0: write fp32 C.   OMODE 1: write bf16 hi/lo split of C.
// ---------------------------------------------------------------------------
#define GBM 128
#define GBN 128
#define GBK 32
#define APITCH 40
#define BPITCH 136
#define ASZ (128*APITCH)
#define BSZ (32*BPITCH)

template<int OMODE>
__global__ __launch_bounds__(256, 1) void gemm_bf16x3(
    const bf16* __restrict__ Agh, const bf16* __restrict__ Agl,
    const bf16* __restrict__ Bgh, const bf16* __restrict__ Bgl,
    const float* __restrict__ bias,
    float* __restrict__ C, bf16* __restrict__ Ch, bf16* __restrict__ Cl,
    int M, int N, int K)
{
    extern __shared__ char smem[];
    bf16* sAh = (bf16*)smem;
    bf16* sAl = sAh + 2 * ASZ;
    bf16* sBh = sAl + 2 * ASZ;
    bf16* sBl = sBh + 2 * BSZ;

    const int tid  = threadIdx.x;
    const int lane = tid & 31;
    const int warp = tid >> 5;
    const int bm   = blockIdx.y * GBM;
    const int bn   = blockIdx.x * GBN;
    const int wm   = (warp & 1) * 64;
    const int wn   = (warp >> 1) * 32;

    float acc[4][4][4];
#pragma unroll
    for (int mi = 0; mi < 4; mi++)
#pragma unroll
        for (int n = 0; n < 4; n++)
#pragma unroll
            for (int e = 0; e < 4; e++) acc[mi][n][e] = 0.f;

    auto prefetch = [&](int st, int k0) {
        const bf16* ah = Agh + (size_t)bm * K + k0;
        const bf16* al = Agl + (size_t)bm * K + k0;
#pragma unroll
        for (int i = 0; i < 2; i++) {
            int idx = tid + i * 256;
            int r = idx >> 2, c = (idx & 3) * 8;
            cpa16(sptr(&sAh[st * ASZ + r * APITCH + c]), ah + (size_t)r * K + c);
            cpa16(sptr(&sAl[st * ASZ + r * APITCH + c]), al + (size_t)r * K + c);
        }
        const bf16* bh = Bgh + (size_t)k0 * N + bn;
        const bf16* bl = Bgl + (size_t)k0 * N + bn;
#pragma unroll
        for (int i = 0; i < 2; i++) {
            int idx = tid + i * 256;
            int r = idx >> 4, c = (idx & 15) * 8;
            cpa16(sptr(&sBh[st * BSZ + r * BPITCH + c]), bh + (size_t)r * N + c);
            cpa16(sptr(&sBl[st * BSZ + r * BPITCH + c]), bl + (size_t)r * N + c);
        }
        asm volatile("cp.async.commit_group;");
    };

    const int NIT = K / GBK;
    prefetch(0, 0);
    for (int it = 0; it < NIT; it++) {
        if (it + 1 < NIT) {
            prefetch((it + 1) & 1, (it + 1) * GBK);
            asm volatile("cp.async.wait_group 1;");
        } else {
            asm volatile("cp.async.wait_group 0;");
        }
        __syncthreads();
        const int st = it & 1;

#pragma unroll
        for (int kk = 0; kk < GBK; kk += 16) {
            unsigned ah[4][4], al[4][4], bh[2][4], bl[2][4];
#pragma unroll
            for (int mi = 0; mi < 4; mi++) {
                int row = wm + mi * 16 + (lane & 15);
                int col = kk + (lane >> 4) * 8;
                ldsm4(ah[mi], sptr(&sAh[st * ASZ + row * APITCH + col]));
                ldsm4(al[mi], sptr(&sAl[st * ASZ + row * APITCH + col]));
            }
#pragma unroll
            for (int nj = 0; nj < 2; nj++) {
                int row = kk + (lane & 15);
                int col = wn + nj * 16 + (lane >> 4) * 8;
                ldsm4t(bh[nj], sptr(&sBh[st * BSZ + row * BPITCH + col]));
                ldsm4t(bl[nj], sptr(&sBl[st * BSZ + row * BPITCH + col]));
            }
            // pass 1: Ah @ Bh  (16 independent MMAs)
#pragma unroll
            for (int mi = 0; mi < 4; mi++)
#pragma unroll
                for (int nj = 0; nj < 2; nj++)
#pragma unroll
                    for (int sub = 0; sub < 2; sub++)
                        mma16816(acc[mi][nj * 2 + sub], ah[mi], &bh[nj][sub * 2]);
            // pass 2: Ah @ Bl
#pragma unroll
            for (int mi = 0; mi < 4; mi++)
#pragma unroll
                for (int nj = 0; nj < 2; nj++)
#pragma unroll
                    for (int sub = 0; sub < 2; sub++)
                        mma16816(acc[mi][nj * 2 + sub], ah[mi], &bl[nj][sub * 2]);
            // pass 3: Al @ Bh
#pragma unroll
            for (int mi = 0; mi < 4; mi++)
#pragma unroll
                for (int nj = 0; nj < 2; nj++)
#pragma unroll
                    for (int sub = 0; sub < 2; sub++)
                        mma16816(acc[mi][nj * 2 + sub], al[mi], &bh[nj][sub * 2]);
        }
        __syncthreads();
    }

#pragma unroll
    for (int mi = 0; mi < 4; mi++) {
        int r0 = bm + wm + mi * 16 + (lane >> 2);
#pragma unroll
        for (int n = 0; n < 4; n++) {
            int c0 = bn + wn + n * 8 + (lane & 3) * 2;
            float2 bv = *(const float2*)(bias + c0);
            float v00 = acc[mi][n][0] + bv.x, v01 = acc[mi][n][1] + bv.y;
            float v10 = acc[mi][n][2] + bv.x, v11 = acc[mi][n][3] + bv.y;
            if (OMODE == 0) {
                *(float2*)(C + (size_t)r0 * N + c0) = make_float2(v00, v01);
                *(float2*)(C + (size_t)(r0 + 8) * N + c0) = make_float2(v10, v11);
            } else {
                unsigned h0, l0, h1, l1;
                split2(v00, v01, h0, l0);
                split2(v10, v11, h1, l1);
                *(unsigned*)(Ch + (size_t)r0 * N + c0) = h0;
                *(unsigned*)(Cl + (size_t)r0 * N + c0) = l0;
                *(unsigned*)(Ch + (size_t)(r0 + 8) * N + c0) = h1;
                *(unsigned*)(Cl + (size_t)(r0 + 8) * N + c0) = l1;
            }
        }
    }
}

// ---------------------------------------------------------------------------
// Tensor-core causal flash attention. MMAs grouped in term passes over
// fragment pairs -> accumulator reuse distance 4.
// ---------------------------------------------------------------------------
#define KP 72
#define TSZ (64*KP)
#define STG (4*TSZ)
#define FLASH_SMEM (2*STG*2)

__global__ __launch_bounds__(256, 1) void flash_attn_mma(
    const bf16* __restrict__ qvh, const bf16* __restrict__ qvl,
    bf16* __restrict__ outh, bf16* __restrict__ outl)
{
    extern __shared__ char smraw[];
    bf16* sm = (bf16*)smraw;

    const int tid  = threadIdx.x;
    const int lane = tid & 31;
    const int warp = tid >> 5;
    const int bh   = blockIdx.y;
    const int b    = bh >> 4;
    const int h    = bh & (NHEAD - 1);
    const int qb   = (gridDim.x - 1) - blockIdx.x;
    const int q0   = qb * 128;
    const int wm   = warp * 16;
    const int r    = lane >> 2;
    const int cp   = (lane & 3) * 2;
    const int qrow = q0 + wm + r;

    unsigned qfh[4][4], qfl[4][4];
    {
        const size_t base  = ((size_t)(b * SEQ) + qrow) * QKV_N + h * HDIM;
        const size_t base8 = base + (size_t)8 * QKV_N;
#pragma unroll
        for (int kk = 0; kk < 4; kk++) {
            int c0 = kk * 16 + cp;
            qfh[kk][0] = *(const unsigned*)(qvh + base  + c0);
            qfh[kk][1] = *(const unsigned*)(qvh + base8 + c0);
            qfh[kk][2] = *(const unsigned*)(qvh + base  + c0 + 8);
            qfh[kk][3] = *(const unsigned*)(qvh + base8 + c0 + 8);
            qfl[kk][0] = *(const unsigned*)(qvl + base  + c0);
            qfl[kk][1] = *(const unsigned*)(qvl + base8 + c0);
            qfl[kk][2] = *(const unsigned*)(qvl + base  + c0 + 8);
            qfl[kk][3] = *(const unsigned*)(qvl + base8 + c0 + 8);
        }
    }

    float m0 = -1e30f, m1 = -1e30f, l0 = 0.f, l1 = 0.f;
    float o[8][4];
#pragma unroll
    for (int nf = 0; nf < 8; nf++)
#pragma unroll
        for (int e = 0; e < 4; e++) o[nf][e] = 0.f;

    const size_t koff = (size_t)EMBD + h * HDIM;
    const size_t voff = (size_t)(2 * EMBD) + h * HDIM;

    auto prefetch = [&](int st, int k0) {
#pragma unroll
        for (int i = 0; i < 8; i++) {
            int id = tid + i * 256;
            int t  = id >> 9;
            int rr = (id >> 3) & 63;
            int cc = (id & 7) * 8;
            const bf16* src = ((t & 1) ? qvl : qvh)
                            + ((size_t)(b * SEQ) + k0 + rr) * QKV_N
                            + ((t >= 2) ? voff : koff) + cc;
            cpa16(sptr(&sm[st * STG + t * TSZ + rr * KP + cc]), src);
        }
        asm volatile("cp.async.commit_group;");
    };

    const int ntiles = 2 * qb + 2;
    prefetch(0, 0);
    for (int t = 0; t < ntiles; t++) {
        const int k0 = t * 64;
        if (t + 1 < ntiles) {
            prefetch((t + 1) & 1, (t + 1) * 64);
            asm volatile("cp.async.wait_group 1;");
        } else {
            asm volatile("cp.async.wait_group 0;");
        }
        __syncthreads();
        const int st = t & 1;

        if (k0 <= q0 + wm + 15) {
            const bf16* Kh = sm + st * STG + 0 * TSZ;
            const bf16* Kl = sm + st * STG + 1 * TSZ;
            const bf16* Vh = sm + st * STG + 2 * TSZ;
            const bf16* Vl = sm + st * STG + 3 * TSZ;

            // ---- S = Q K^T ----
            float s[8][4];
#pragma unroll
            for (int nf = 0; nf < 8; nf++)
#pragma unroll
                for (int e = 0; e < 4; e++) s[nf][e] = 0.f;

#pragma unroll
            for (int kk = 0; kk < 4; kk++) {
#pragma unroll
                for (int gp = 0; gp < 2; gp++) {
                    unsigned kh4[2][4], kl4[2][4];
#pragma unroll
                    for (int j = 0; j < 2; j++) {
                        int g = gp * 2 + j;
                        int off = (16 * g + (lane & 15)) * KP + kk * 16 + (lane >> 4) * 8;
                        ldsm4(kh4[j], sptr(Kh + off));
                        ldsm4(kl4[j], sptr(Kl + off));
                    }
                    // term pass hh over 4 accumulators
#pragma unroll
                    for (int j = 0; j < 2; j++) {
                        unsigned b0[2] = {kh4[j][0], kh4[j][2]}, b1[2] = {kh4[j][1], kh4[j][3]};
                        mma16816(s[4*gp + 2*j],     qfh[kk], b0);
                        mma16816(s[4*gp + 2*j + 1], qfh[kk], b1);
                    }
                    // term pass hl
#pragma unroll
                    for (int j = 0; j < 2; j++) {
                        unsigned b0[2] = {kl4[j][0], kl4[j][2]}, b1[2] = {kl4[j][1], kl4[j][3]};
                        mma16816(s[4*gp + 2*j],     qfh[kk], b0);
                        mma16816(s[4*gp + 2*j + 1], qfh[kk], b1);
                    }
                    // term pass lh
#pragma unroll
                    for (int j = 0; j < 2; j++) {
                        unsigned b0[2] = {kh4[j][0], kh4[j][2]}, b1[2] = {kh4[j][1], kh4[j][3]};
                        mma16816(s[4*gp + 2*j],     qfl[kk], b0);
                        mma16816(s[4*gp + 2*j + 1], qfl[kk], b1);
                    }
                }
            }

            // ---- masking + online softmax ----
            const bool need_mask = (k0 + 63) > (q0 + wm);
            float mx0 = -1e30f, mx1 = -1e30f;
#pragma unroll
            for (int nf = 0; nf < 8; nf++) {
#pragma unroll
                for (int e = 0; e < 4; e++) s[nf][e] *= 0.125f;
                if (need_mask) {
                    int c0 = k0 + nf * 8 + cp;
                    if (c0     > qrow)     s[nf][0] = -1e30f;
                    if (c0 + 1 > qrow)     s[nf][1] = -1e30f;
                    if (c0     > qrow + 8) s[nf][2] = -1e30f;
                    if (c0 + 1 > qrow + 8) s[nf][3] = -1e30f;
                }
                mx0 = fmaxf(mx0, fmaxf(s[nf][0], s[nf][1]));
                mx1 = fmaxf(mx1, fmaxf(s[nf][2], s[nf][3]));
            }
            mx0 = fmaxf(mx0, __shfl_xor_sync(0xffffffffu, mx0, 1));
            mx0 = fmaxf(mx0, __shfl_xor_sync(0xffffffffu, mx0, 2));
            mx1 = fmaxf(mx1, __shfl_xor_sync(0xffffffffu, mx1, 1));
            mx1 = fmaxf(mx1, __shfl_xor_sync(0xffffffffu, mx1, 2));

            const float nm0 = fmaxf(m0, mx0), nm1 = fmaxf(m1, mx1);
            const float cr0 = __expf(m0 - nm0), cr1 = __expf(m1 - nm1);
            m0 = nm0; m1 = nm1;
            l0 *= cr0; l1 *= cr1;
#pragma unroll
            for (int nf = 0; nf < 8; nf++) {
                o[nf][0] *= cr0; o[nf][1] *= cr0;
                o[nf][2] *= cr1; o[nf][3] *= cr1;
            }

            unsigned ph[8][2], pl[8][2];
#pragma unroll
            for (int nf = 0; nf < 8; nf++) {
                float p0 = __expf(s[nf][0] - m0);
                float p1 = __expf(s[nf][1] - m0);
                float p2 = __expf(s[nf][2] - m1);
                float p3 = __expf(s[nf][3] - m1);
                l0 += p0 + p1;
                l1 += p2 + p3;
                split2(p0, p1, ph[nf][0], pl[nf][0]);
                split2(p2, p3, ph[nf][1], pl[nf][1]);
            }

            // ---- O += P V ----
#pragma unroll
            for (int kp = 0; kp < 4; kp++) {
                unsigned pah[4] = {ph[2*kp][0], ph[2*kp][1], ph[2*kp+1][0], ph[2*kp+1][1]};
                unsigned pal[4] = {pl[2*kp][0], pl[2*kp][1], pl[2*kp+1][0], pl[2*kp+1][1]};
#pragma unroll
                for (int dgp = 0; dgp < 2; dgp++) {
                    unsigned vh4[2][4], vl4[2][4];
#pragma unroll
                    for (int j = 0; j < 2; j++) {
                        int dg = dgp * 2 + j;
                        int off = (kp * 16 + (lane & 15)) * KP + dg * 16 + (lane >> 4) * 8;
                        ldsm4t(vh4[j], sptr(Vh + off));
                        ldsm4t(vl4[j], sptr(Vl + off));
                    }
                    // term pass hh over 4 accumulators
#pragma unroll
                    for (int j = 0; j < 2; j++) {
                        mma16816(o[4*dgp + 2*j],     pah, &vh4[j][0]);
                        mma16816(o[4*dgp + 2*j + 1], pah, &vh4[j][2]);
                    }
                    // term pass hl
#pragma unroll
                    for (int j = 0; j < 2; j++) {
                        mma16816(o[4*dgp + 2*j],     pah, &vl4[j][0]);
                        mma16816(o[4*dgp + 2*j + 1], pah, &vl4[j][2]);
                    }
                    // term pass lh
#pragma unroll
                    for (int j = 0; j < 2; j++) {
                        mma16816(o[4*dgp + 2*j],     pal, &vh4[j][0]);
                        mma16816(o[4*dgp + 2*j + 1], pal, &vh4[j][2]);
                    }
                }
            }
        }
        __syncthreads();
    }

    l0 += __shfl_xor_sync(0xffffffffu, l0, 1);
    l0 += __shfl_xor_sync(0xffffffffu, l0, 2);
    l1 += __shfl_xor_sync(0xffffffffu, l1, 1);
    l1 += __shfl_xor_sync(0xffffffffu, l1, 2);
    const float inv0 = 1.f / l0, inv1 = 1.f / l1;

    const size_t obase  = ((size_t)(b * SEQ) + qrow) * EMBD + h * HDIM;
    const size_t obase8 = obase + (size_t)8 * EMBD;
#pragma unroll
    for (int nf = 0; nf < 8; nf++) {
        int c0 = nf * 8 + cp;
        unsigned h0, lo0, h1, lo1;
        split2(o[nf][0] * inv0, o[nf][1] * inv0, h0, lo0);
        split2(o[nf][2] * inv1, o[nf][3] * inv1, h1, lo1);
        *(unsigned*)(outh + obase  + c0) = h0;
        *(unsigned*)(outl + obase  + c0) = lo0;
        *(unsigned*)(outh + obase8 + c0) = h1;
        *(unsigned*)(outl + obase8 + c0) = lo1;
    }
}

// ---------------------------------------------------------------------------
// Launch
// ---------------------------------------------------------------------------
extern "C" void kernel_launch(void* const* d_in, const int* in_sizes, int n_in,
                              void* d_out, int out_size)
{
    const float* x     = (const float*)d_in[0];
    const float* W_qkv = (const float*)d_in[1];
    const float* b_qkv = (const float*)d_in[2];
    const float* W_out = (const float*)d_in[3];
    const float* b_out = (const float*)d_in[4];
    float* out = (float*)d_out;

    bf16 *xh, *xl, *wqh, *wql, *woh, *wol, *qkvh, *qkvl, *ah, *al;
    cudaGetSymbolAddress((void**)&xh,   g_xh);
    cudaGetSymbolAddress((void**)&xl,   g_xl);
    cudaGetSymbolAddress((void**)&wqh,  g_wqh);
    cudaGetSymbolAddress((void**)&wql,  g_wql);
    cudaGetSymbolAddress((void**)&woh,  g_woh);
    cudaGetSymbolAddress((void**)&wol,  g_wol);
    cudaGetSymbolAddress((void**)&qkvh, g_qkvh);
    cudaGetSymbolAddress((void**)&qkvl, g_qkvl);
    cudaGetSymbolAddress((void**)&ah,   g_ah);
    cudaGetSymbolAddress((void**)&al,   g_al);

    const int M = BATCH * SEQ;                       // 8192
    const int SMEM_GEMM = (4*ASZ + 4*BSZ) * (int)sizeof(bf16);   // 75776
    cudaFuncSetAttribute(gemm_bf16x3<0>, cudaFuncAttributeMaxDynamicSharedMemorySize, SMEM_GEMM);
    cudaFuncSetAttribute(gemm_bf16x3<1>, cudaFuncAttributeMaxDynamicSharedMemorySize, SMEM_GEMM);
    cudaFuncSetAttribute(flash_attn_mma, cudaFuncAttributeMaxDynamicSharedMemorySize, FLASH_SMEM);

    // 1) split inputs into bf16 hi/lo
    {
        int n4 = M * EMBD / 4;
        split_bf16x4<<<(n4 + 255) / 256, 256>>>((const float4*)x, (uint2*)xh, (uint2*)xl, n4);
        n4 = EMBD * QKV_N / 4;
        split_bf16x4<<<(n4 + 255) / 256, 256>>>((const float4*)W_qkv, (uint2*)wqh, (uint2*)wql, n4);
        n4 = EMBD * EMBD / 4;
        split_bf16x4<<<(n4 + 255) / 256, 256>>>((const float4*)W_out, (uint2*)woh, (uint2*)wol, n4);
    }
    // 2) QKV projection -> bf16 hi/lo qkv directly
    {
        dim3 grid(QKV_N / GBN, M / GBM);
        gemm_bf16x3<1><<<grid, 256, SMEM_GEMM>>>(xh, xl, wqh, wql, b_qkv,
                                                 nullptr, qkvh, qkvl, M, QKV_N, EMBD);
    }
    // 3) Tensor-core flash attention -> bf16 hi/lo attn output
    {
        dim3 grid(SEQ / 128, BATCH * NHEAD);
        flash_attn_mma<<<grid, 256, FLASH_SMEM>>>(qkvh, qkvl, ah, al);
    }
    // 4) Output projection -> fp32 result
    {
        dim3 grid(EMBD / GBN, M / GBM);
        gemm_bf16x3<0><<<grid, 256, SMEM_GEMM>>>(ah, al, woh, wol, b_out,
                                                 out, nullptr, nullptr, M, EMBD, EMBD);
    }
}

// round 8
// speedup vs baseline: 1.4704x; 1.4704x over previous
#include <cuda_runtime.h>
#include <cuda_bf16.h>
#include <cuda_fp16.h>

// Problem constants
#define BATCH 4
#define SEQ   2048
#define EMBD  1024
#define NHEAD 16
#define HDIM  64
#define QKV_N (3*EMBD)

typedef __nv_bfloat16 bf16;

// ---------------------------------------------------------------------------
// Scratch (device globals: allocation-free, graph-capture safe)
// ---------------------------------------------------------------------------
__device__ __align__(256) bf16 g_xh[(size_t)BATCH * SEQ * EMBD];
__device__ __align__(256) bf16 g_xl[(size_t)BATCH * SEQ * EMBD];
__device__ __align__(256) bf16 g_wqh[(size_t)EMBD * QKV_N];
__device__ __align__(256) bf16 g_wql[(size_t)EMBD * QKV_N];
__device__ __align__(256) bf16 g_woh[(size_t)EMBD * EMBD];
__device__ __align__(256) bf16 g_wol[(size_t)EMBD * EMBD];
__device__ __align__(256) __half g_qkvf[(size_t)BATCH * SEQ * QKV_N];  // fp16 qkv
__device__ __align__(256) bf16 g_ah[(size_t)BATCH * SEQ * EMBD];
__device__ __align__(256) bf16 g_al[(size_t)BATCH * SEQ * EMBD];

// ---------------------------------------------------------------------------
// Common PTX helpers
// ---------------------------------------------------------------------------
__device__ __forceinline__ unsigned sptr(const void* p) {
    return (unsigned)__cvta_generic_to_shared(p);
}
__device__ __forceinline__ void cpa16(unsigned s, const void* g) {
    asm volatile("cp.async.cg.shared.global [%0], [%1], 16;\n" :: "r"(s), "l"(g));
}
__device__ __forceinline__ void ldsm4(unsigned* r, unsigned a) {
    asm volatile("ldmatrix.sync.aligned.m8n8.x4.shared.b16 {%0,%1,%2,%3},[%4];"
                 : "=r"(r[0]), "=r"(r[1]), "=r"(r[2]), "=r"(r[3]) : "r"(a));
}
__device__ __forceinline__ void ldsm4t(unsigned* r, unsigned a) {
    asm volatile("ldmatrix.sync.aligned.m8n8.x4.trans.shared.b16 {%0,%1,%2,%3},[%4];"
                 : "=r"(r[0]), "=r"(r[1]), "=r"(r[2]), "=r"(r[3]) : "r"(a));
}
__device__ __forceinline__ void mma16816(float* d, const unsigned* a, const unsigned* b) {
    asm volatile(
        "mma.sync.aligned.m16n8k16.row.col.f32.bf16.bf16.f32 "
        "{%0,%1,%2,%3},{%4,%5,%6,%7},{%8,%9},{%0,%1,%2,%3};"
        : "+f"(d[0]), "+f"(d[1]), "+f"(d[2]), "+f"(d[3])
        : "r"(a[0]), "r"(a[1]), "r"(a[2]), "r"(a[3]), "r"(b[0]), "r"(b[1]));
}
__device__ __forceinline__ void mma16816h(float* d, const unsigned* a, const unsigned* b) {
    asm volatile(
        "mma.sync.aligned.m16n8k16.row.col.f32.f16.f16.f32 "
        "{%0,%1,%2,%3},{%4,%5,%6,%7},{%8,%9},{%0,%1,%2,%3};"
        : "+f"(d[0]), "+f"(d[1]), "+f"(d[2]), "+f"(d[3])
        : "r"(a[0]), "r"(a[1]), "r"(a[2]), "r"(a[3]), "r"(b[0]), "r"(b[1]));
}
// split fp32 pair -> packed bf16x2 hi + lo
__device__ __forceinline__ void split2(float a, float b, unsigned& h, unsigned& l) {
    bf16 ah = __float2bfloat16_rn(a);
    bf16 bh = __float2bfloat16_rn(b);
    bf16 al = __float2bfloat16_rn(a - __bfloat162float(ah));
    bf16 bl = __float2bfloat16_rn(b - __bfloat162float(bh));
    h = (unsigned)__bfloat16_as_ushort(ah) | ((unsigned)__bfloat16_as_ushort(bh) << 16);
    l = (unsigned)__bfloat16_as_ushort(al) | ((unsigned)__bfloat16_as_ushort(bl) << 16);
}
__device__ __forceinline__ unsigned packh2(float a, float b) {
    __half2 hv = __floats2half2_rn(a, b);
    return *(unsigned*)&hv;
}

// ---------------------------------------------------------------------------
// fp32 -> (bf16 hi, bf16 lo) split, vectorized x4
// ---------------------------------------------------------------------------
__global__ __launch_bounds__(256) void split_bf16x4(
    const float4* __restrict__ in, uint2* __restrict__ hi, uint2* __restrict__ lo, int n4)
{
    int i = blockIdx.x * blockDim.x + threadIdx.x;
    if (i >= n4) return;
    float4 v = in[i];
    uint2 ho, loo;
    split2(v.x, v.y, ho.x, loo.x);
    split2(v.z, v.w, ho.y, loo.y);
    hi[i] = ho;
    lo[i] = loo;
}

// ---------------------------------------------------------------------------
// Tensor-core GEMM, bf16x3 emulated fp32: C = Ah@Bh + Ah@Bl + Al@Bh + bias
// 128 threads, 4 warps, warp tile 64x64, CTA tile 128x128, 2 CTAs/SM.
// OMODE 0: write fp32 C.   OMODE 2: write fp16 C.
// ---------------------------------------------------------------------------
#define GBM 128
#define GBN 128
#define GBK 32
#define APITCH 40
#define BPITCH 136
#define ASZ (128*APITCH)
#define BSZ (32*BPITCH)

template<int OMODE>
__global__ __launch_bounds__(128, 2) void gemm_bf16x3(
    const bf16* __restrict__ Agh, const bf16* __restrict__ Agl,
    const bf16* __restrict__ Bgh, const bf16* __restrict__ Bgl,
    const float* __restrict__ bias,
    float* __restrict__ C, __half* __restrict__ Cf,
    int M, int N, int K)
{
    extern __shared__ char smem[];
    bf16* sAh = (bf16*)smem;
    bf16* sAl = sAh + 2 * ASZ;
    bf16* sBh = sAl + 2 * ASZ;
    bf16* sBl = sBh + 2 * BSZ;

    const int tid  = threadIdx.x;
    const int lane = tid & 31;
    const int warp = tid >> 5;
    const int bm   = blockIdx.y * GBM;
    const int bn   = blockIdx.x * GBN;
    const int wm   = (warp & 1) * 64;
    const int wn   = (warp >> 1) * 64;

    float acc[4][8][4];
#pragma unroll
    for (int mi = 0; mi < 4; mi++)
#pragma unroll
        for (int n = 0; n < 8; n++)
#pragma unroll
            for (int e = 0; e < 4; e++) acc[mi][n][e] = 0.f;

    auto prefetch = [&](int st, int k0) {
        const bf16* ah = Agh + (size_t)bm * K + k0;
        const bf16* al = Agl + (size_t)bm * K + k0;
#pragma unroll
        for (int i = 0; i < 4; i++) {
            int idx = tid + i * 128;
            int r = idx >> 2, c = (idx & 3) * 8;
            cpa16(sptr(&sAh[st * ASZ + r * APITCH + c]), ah + (size_t)r * K + c);
            cpa16(sptr(&sAl[st * ASZ + r * APITCH + c]), al + (size_t)r * K + c);
        }
        const bf16* bh = Bgh + (size_t)k0 * N + bn;
        const bf16* bl = Bgl + (size_t)k0 * N + bn;
#pragma unroll
        for (int i = 0; i < 4; i++) {
            int idx = tid + i * 128;
            int r = idx >> 4, c = (idx & 15) * 8;
            cpa16(sptr(&sBh[st * BSZ + r * BPITCH + c]), bh + (size_t)r * N + c);
            cpa16(sptr(&sBl[st * BSZ + r * BPITCH + c]), bl + (size_t)r * N + c);
        }
        asm volatile("cp.async.commit_group;");
    };

    const int NIT = K / GBK;
    prefetch(0, 0);
    for (int it = 0; it < NIT; it++) {
        if (it + 1 < NIT) {
            prefetch((it + 1) & 1, (it + 1) * GBK);
            asm volatile("cp.async.wait_group 1;");
        } else {
            asm volatile("cp.async.wait_group 0;");
        }
        __syncthreads();
        const int st = it & 1;

#pragma unroll
        for (int kk = 0; kk < GBK; kk += 16) {
            unsigned ah[4][4], al[4][4], bh[4][4], bl[4][4];
#pragma unroll
            for (int mi = 0; mi < 4; mi++) {
                int row = wm + mi * 16 + (lane & 15);
                int col = kk + (lane >> 4) * 8;
                ldsm4(ah[mi], sptr(&sAh[st * ASZ + row * APITCH + col]));
                ldsm4(al[mi], sptr(&sAl[st * ASZ + row * APITCH + col]));
            }
#pragma unroll
            for (int nj = 0; nj < 4; nj++) {
                int row = kk + (lane & 15);
                int col = wn + nj * 16 + (lane >> 4) * 8;
                ldsm4t(bh[nj], sptr(&sBh[st * BSZ + row * BPITCH + col]));
                ldsm4t(bl[nj], sptr(&sBl[st * BSZ + row * BPITCH + col]));
            }
#pragma unroll
            for (int mi = 0; mi < 4; mi++)
#pragma unroll
                for (int nj = 0; nj < 4; nj++)
#pragma unroll
                    for (int sub = 0; sub < 2; sub++)
                        mma16816(acc[mi][nj * 2 + sub], ah[mi], &bh[nj][sub * 2]);
#pragma unroll
            for (int mi = 0; mi < 4; mi++)
#pragma unroll
                for (int nj = 0; nj < 4; nj++)
#pragma unroll
                    for (int sub = 0; sub < 2; sub++)
                        mma16816(acc[mi][nj * 2 + sub], ah[mi], &bl[nj][sub * 2]);
#pragma unroll
            for (int mi = 0; mi < 4; mi++)
#pragma unroll
                for (int nj = 0; nj < 4; nj++)
#pragma unroll
                    for (int sub = 0; sub < 2; sub++)
                        mma16816(acc[mi][nj * 2 + sub], al[mi], &bh[nj][sub * 2]);
        }
        __syncthreads();
    }

#pragma unroll
    for (int mi = 0; mi < 4; mi++) {
        int r0 = bm + wm + mi * 16 + (lane >> 2);
#pragma unroll
        for (int n = 0; n < 8; n++) {
            int c0 = bn + wn + n * 8 + (lane & 3) * 2;
            float2 bv = *(const float2*)(bias + c0);
            float v00 = acc[mi][n][0] + bv.x, v01 = acc[mi][n][1] + bv.y;
            float v10 = acc[mi][n][2] + bv.x, v11 = acc[mi][n][3] + bv.y;
            if (OMODE == 0) {
                *(float2*)(C + (size_t)r0 * N + c0) = make_float2(v00, v01);
                *(float2*)(C + (size_t)(r0 + 8) * N + c0) = make_float2(v10, v11);
            } else {
                *(unsigned*)(Cf + (size_t)r0 * N + c0) = packh2(v00, v01);
                *(unsigned*)(Cf + (size_t)(r0 + 8) * N + c0) = packh2(v10, v11);
            }
        }
    }
}

// ---------------------------------------------------------------------------
// Tensor-core causal flash attention, single fp16 MMA path.
// Q,K,V,P fp16; accumulation fp32; output written bf16 hi/lo.
// ---------------------------------------------------------------------------
#define KPH 72
#define TSZH (64*KPH)              // halves per tile
#define STGH (2*TSZH)              // K, V
#define FLASH_SMEM (2*STGH*2)      // bytes (36864)

__global__ __launch_bounds__(256, 2) void flash_attn_mma(
    const __half* __restrict__ qkv,
    bf16* __restrict__ outh, bf16* __restrict__ outl)
{
    extern __shared__ char smraw[];
    __half* sm = (__half*)smraw;

    const int tid  = threadIdx.x;
    const int lane = tid & 31;
    const int warp = tid >> 5;
    const int bh   = blockIdx.y;
    const int b    = bh >> 4;
    const int h    = bh & (NHEAD - 1);
    const int qb   = (gridDim.x - 1) - blockIdx.x;  // heavy tiles first
    const int q0   = qb * 128;
    const int wm   = warp * 16;
    const int r    = lane >> 2;
    const int cp   = (lane & 3) * 2;
    const int qrow = q0 + wm + r;

    // ---- Q fragments straight from global (packed half2 = one u32) ----
    unsigned qf[4][4];
    {
        const size_t base  = ((size_t)(b * SEQ) + qrow) * QKV_N + h * HDIM;
        const size_t base8 = base + (size_t)8 * QKV_N;
#pragma unroll
        for (int kk = 0; kk < 4; kk++) {
            int c0 = kk * 16 + cp;
            qf[kk][0] = *(const unsigned*)(qkv + base  + c0);
            qf[kk][1] = *(const unsigned*)(qkv + base8 + c0);
            qf[kk][2] = *(const unsigned*)(qkv + base  + c0 + 8);
            qf[kk][3] = *(const unsigned*)(qkv + base8 + c0 + 8);
        }
    }

    float m0 = -1e30f, m1 = -1e30f, l0 = 0.f, l1 = 0.f;
    float o[8][4];
#pragma unroll
    for (int nf = 0; nf < 8; nf++)
#pragma unroll
        for (int e = 0; e < 4; e++) o[nf][e] = 0.f;

    const size_t koff = (size_t)EMBD + h * HDIM;
    const size_t voff = (size_t)(2 * EMBD) + h * HDIM;

    auto prefetch = [&](int st, int k0) {
#pragma unroll
        for (int i = 0; i < 4; i++) {
            int id = tid + i * 256;           // 0..1023
            int t  = id >> 9;                 // 0:K 1:V
            int rr = (id >> 3) & 63;
            int cc = (id & 7) * 8;
            const __half* src = qkv + ((size_t)(b * SEQ) + k0 + rr) * QKV_N
                              + (t ? voff : koff) + cc;
            cpa16(sptr(&sm[st * STGH + t * TSZH + rr * KPH + cc]), src);
        }
        asm volatile("cp.async.commit_group;");
    };

    const int ntiles = 2 * qb + 2;
    prefetch(0, 0);
    for (int t = 0; t < ntiles; t++) {
        const int k0 = t * 64;
        if (t + 1 < ntiles) {
            prefetch((t + 1) & 1, (t + 1) * 64);
            asm volatile("cp.async.wait_group 1;");
        } else {
            asm volatile("cp.async.wait_group 0;");
        }
        __syncthreads();
        const int st = t & 1;

        if (k0 <= q0 + wm + 15) {   // causal warp-level skip
            const __half* Kf = sm + st * STGH;
            const __half* Vf = sm + st * STGH + TSZH;

            // ---- S = Q K^T (single fp16 term) ----
            float s[8][4];
#pragma unroll
            for (int nf = 0; nf < 8; nf++)
#pragma unroll
                for (int e = 0; e < 4; e++) s[nf][e] = 0.f;

#pragma unroll
            for (int kk = 0; kk < 4; kk++) {
#pragma unroll
                for (int g = 0; g < 4; g++) {
                    unsigned kf4[4];
                    int off = (16 * g + (lane & 15)) * KPH + kk * 16 + (lane >> 4) * 8;
                    ldsm4(kf4, sptr(Kf + off));
                    unsigned b0[2] = {kf4[0], kf4[2]}, b1[2] = {kf4[1], kf4[3]};
                    mma16816h(s[2*g],     qf[kk], b0);
                    mma16816h(s[2*g + 1], qf[kk], b1);
                }
            }

            // ---- masking + online softmax ----
            const bool need_mask = (k0 + 63) > (q0 + wm);
            float mx0 = -1e30f, mx1 = -1e30f;
#pragma unroll
            for (int nf = 0; nf < 8; nf++) {
#pragma unroll
                for (int e = 0; e < 4; e++) s[nf][e] *= 0.125f;
                if (need_mask) {
                    int c0 = k0 + nf * 8 + cp;
                    if (c0     > qrow)     s[nf][0] = -1e30f;
                    if (c0 + 1 > qrow)     s[nf][1] = -1e30f;
                    if (c0     > qrow + 8) s[nf][2] = -1e30f;
                    if (c0 + 1 > qrow + 8) s[nf][3] = -1e30f;
                }
                mx0 = fmaxf(mx0, fmaxf(s[nf][0], s[nf][1]));
                mx1 = fmaxf(mx1, fmaxf(s[nf][2], s[nf][3]));
            }
            mx0 = fmaxf(mx0, __shfl_xor_sync(0xffffffffu, mx0, 1));
            mx0 = fmaxf(mx0, __shfl_xor_sync(0xffffffffu, mx0, 2));
            mx1 = fmaxf(mx1, __shfl_xor_sync(0xffffffffu, mx1, 1));
            mx1 = fmaxf(mx1, __shfl_xor_sync(0xffffffffu, mx1, 2));

            const float nm0 = fmaxf(m0, mx0), nm1 = fmaxf(m1, mx1);
            const float cr0 = __expf(m0 - nm0), cr1 = __expf(m1 - nm1);
            m0 = nm0; m1 = nm1;
            l0 *= cr0; l1 *= cr1;
#pragma unroll
            for (int nf = 0; nf < 8; nf++) {
                o[nf][0] *= cr0; o[nf][1] *= cr0;
                o[nf][2] *= cr1; o[nf][3] *= cr1;
            }

            unsigned pf[8][2];
#pragma unroll
            for (int nf = 0; nf < 8; nf++) {
                float p0 = __expf(s[nf][0] - m0);
                float p1 = __expf(s[nf][1] - m0);
                float p2 = __expf(s[nf][2] - m1);
                float p3 = __expf(s[nf][3] - m1);
                l0 += p0 + p1;
                l1 += p2 + p3;
                pf[nf][0] = packh2(p0, p1);
                pf[nf][1] = packh2(p2, p3);
            }

            // ---- O += P V (single fp16 term) ----
#pragma unroll
            for (int kp = 0; kp < 4; kp++) {
                unsigned pa[4] = {pf[2*kp][0], pf[2*kp][1], pf[2*kp+1][0], pf[2*kp+1][1]};
#pragma unroll
                for (int dg = 0; dg < 4; dg++) {
                    unsigned vf4[4];
                    int off = (kp * 16 + (lane & 15)) * KPH + dg * 16 + (lane >> 4) * 8;
                    ldsm4t(vf4, sptr(Vf + off));
                    mma16816h(o[2*dg],     pa, &vf4[0]);
                    mma16816h(o[2*dg + 1], pa, &vf4[2]);
                }
            }
        }
        __syncthreads();
    }

    // ---- finalize: quad-reduce l, normalize, split to bf16 hi/lo, store ----
    l0 += __shfl_xor_sync(0xffffffffu, l0, 1);
    l0 += __shfl_xor_sync(0xffffffffu, l0, 2);
    l1 += __shfl_xor_sync(0xffffffffu, l1, 1);
    l1 += __shfl_xor_sync(0xffffffffu, l1, 2);
    const float inv0 = 1.f / l0, inv1 = 1.f / l1;

    const size_t obase  = ((size_t)(b * SEQ) + qrow) * EMBD + h * HDIM;
    const size_t obase8 = obase + (size_t)8 * EMBD;
#pragma unroll
    for (int nf = 0; nf < 8; nf++) {
        int c0 = nf * 8 + cp;
        unsigned h0, lo0, h1, lo1;
        split2(o[nf][0] * inv0, o[nf][1] * inv0, h0, lo0);
        split2(o[nf][2] * inv1, o[nf][3] * inv1, h1, lo1);
        *(unsigned*)(outh + obase  + c0) = h0;
        *(unsigned*)(outl + obase  + c0) = lo0;
        *(unsigned*)(outh + obase8 + c0) = h1;
        *(unsigned*)(outl + obase8 + c0) = lo1;
    }
}

// ---------------------------------------------------------------------------
// Launch
// ---------------------------------------------------------------------------
extern "C" void kernel_launch(void* const* d_in, const int* in_sizes, int n_in,
                              void* d_out, int out_size)
{
    const float* x     = (const float*)d_in[0];
    const float* W_qkv = (const float*)d_in[1];
    const float* b_qkv = (const float*)d_in[2];
    const float* W_out = (const float*)d_in[3];
    const float* b_out = (const float*)d_in[4];
    float* out = (float*)d_out;

    bf16 *xh, *xl, *wqh, *wql, *woh, *wol, *ah, *al;
    __half* qkvf;
    cudaGetSymbolAddress((void**)&xh,   g_xh);
    cudaGetSymbolAddress((void**)&xl,   g_xl);
    cudaGetSymbolAddress((void**)&wqh,  g_wqh);
    cudaGetSymbolAddress((void**)&wql,  g_wql);
    cudaGetSymbolAddress((void**)&woh,  g_woh);
    cudaGetSymbolAddress((void**)&wol,  g_wol);
    cudaGetSymbolAddress((void**)&qkvf, g_qkvf);
    cudaGetSymbolAddress((void**)&ah,   g_ah);
    cudaGetSymbolAddress((void**)&al,   g_al);

    const int M = BATCH * SEQ;                       // 8192
    const int SMEM_GEMM = (4*ASZ + 4*BSZ) * (int)sizeof(bf16);   // 75776
    cudaFuncSetAttribute(gemm_bf16x3<0>, cudaFuncAttributeMaxDynamicSharedMemorySize, SMEM_GEMM);
    cudaFuncSetAttribute(gemm_bf16x3<2>, cudaFuncAttributeMaxDynamicSharedMemorySize, SMEM_GEMM);
    cudaFuncSetAttribute(flash_attn_mma, cudaFuncAttributeMaxDynamicSharedMemorySize, FLASH_SMEM);

    // 1) split inputs into bf16 hi/lo
    {
        int n4 = M * EMBD / 4;
        split_bf16x4<<<(n4 + 255) / 256, 256>>>((const float4*)x, (uint2*)xh, (uint2*)xl, n4);
        n4 = EMBD * QKV_N / 4;
        split_bf16x4<<<(n4 + 255) / 256, 256>>>((const float4*)W_qkv, (uint2*)wqh, (uint2*)wql, n4);
        n4 = EMBD * EMBD / 4;
        split_bf16x4<<<(n4 + 255) / 256, 256>>>((const float4*)W_out, (uint2*)woh, (uint2*)wol, n4);
    }
    // 2) QKV projection (bf16x3) -> fp16 qkv directly
    {
        dim3 grid(QKV_N / GBN, M / GBM);
        gemm_bf16x3<2><<<grid, 128, SMEM_GEMM>>>(xh, xl, wqh, wql, b_qkv,
                                                 nullptr, qkvf, M, QKV_N, EMBD);
    }
    // 3) Flash attention (fp16 single-term MMA) -> bf16 hi/lo attn output
    {
        dim3 grid(SEQ / 128, BATCH * NHEAD);
        flash_attn_mma<<<grid, 256, FLASH_SMEM>>>(qkvf, ah, al);
    }
    // 4) Output projection (bf16x3) -> fp32 result
    {
        dim3 grid(EMBD / GBN, M / GBM);
        gemm_bf16x3<0><<<grid, 128, SMEM_GEMM>>>(ah, al, woh, wol, b_out,
                                                 out, nullptr, M, EMBD, EMBD);
    }
}

// round 10
// speedup vs baseline: 2.7834x; 1.8929x over previous
#include <cuda_runtime.h>
#include <cuda_bf16.h>
#include <cuda_fp16.h>

// Problem constants
#define BATCH 4
#define SEQ   2048
#define EMBD  1024
#define NHEAD 16
#define HDIM  64
#define QKV_N (3*EMBD)

// ---------------------------------------------------------------------------
// Scratch (device globals: allocation-free, graph-capture safe)
// ---------------------------------------------------------------------------
__device__ __align__(256) __half g_xf[(size_t)BATCH * SEQ * EMBD];
__device__ __align__(256) __half g_wqf[(size_t)EMBD * QKV_N];
__device__ __align__(256) __half g_wof[(size_t)EMBD * EMBD];
__device__ __align__(256) __half g_qkvf[(size_t)BATCH * SEQ * QKV_N];
__device__ __align__(256) __half g_af[(size_t)BATCH * SEQ * EMBD];

// ---------------------------------------------------------------------------
// Common PTX helpers
// ---------------------------------------------------------------------------
__device__ __forceinline__ unsigned sptr(const void* p) {
    return (unsigned)__cvta_generic_to_shared(p);
}
__device__ __forceinline__ void cpa16(unsigned s, const void* g) {
    asm volatile("cp.async.cg.shared.global [%0], [%1], 16;\n" :: "r"(s), "l"(g));
}
__device__ __forceinline__ void ldsm4(unsigned* r, unsigned a) {
    asm volatile("ldmatrix.sync.aligned.m8n8.x4.shared.b16 {%0,%1,%2,%3},[%4];"
                 : "=r"(r[0]), "=r"(r[1]), "=r"(r[2]), "=r"(r[3]) : "r"(a));
}
__device__ __forceinline__ void ldsm4t(unsigned* r, unsigned a) {
    asm volatile("ldmatrix.sync.aligned.m8n8.x4.trans.shared.b16 {%0,%1,%2,%3},[%4];"
                 : "=r"(r[0]), "=r"(r[1]), "=r"(r[2]), "=r"(r[3]) : "r"(a));
}
__device__ __forceinline__ void mma16816h(float* d, const unsigned* a, const unsigned* b) {
    asm volatile(
        "mma.sync.aligned.m16n8k16.row.col.f32.f16.f16.f32 "
        "{%0,%1,%2,%3},{%4,%5,%6,%7},{%8,%9},{%0,%1,%2,%3};"
        : "+f"(d[0]), "+f"(d[1]), "+f"(d[2]), "+f"(d[3])
        : "r"(a[0]), "r"(a[1]), "r"(a[2]), "r"(a[3]), "r"(b[0]), "r"(b[1]));
}
__device__ __forceinline__ unsigned packh2(float a, float b) {
    __half2 hv = __floats2half2_rn(a, b);
    return *(unsigned*)&hv;
}

// ---------------------------------------------------------------------------
// fp32 -> fp16 convert, vectorized x4
// ---------------------------------------------------------------------------
__global__ __launch_bounds__(256) void tofp16x4(
    const float4* __restrict__ in, uint2* __restrict__ out, int n4)
{
    int i = blockIdx.x * blockDim.x + threadIdx.x;
    if (i >= n4) return;
    float4 v = in[i];
    uint2 o;
    o.x = packh2(v.x, v.y);
    o.y = packh2(v.z, v.w);
    out[i] = o;
}

// ---------------------------------------------------------------------------
// Tensor-core fp16 GEMM: C[M,N] = A[M,K] @ B[K,N] + bias, fp32 accumulate.
// 128 threads, 4 warps, warp tile 64x64, CTA tile 128x128, 2 CTAs/SM.
// OMODE 0: write fp32 C.   OMODE 2: write fp16 C.
// ---------------------------------------------------------------------------
#define GBM 128
#define GBN 128
#define GBK 32
#define APITCH 40
#define BPITCH 136
#define ASZ (128*APITCH)
#define BSZ (32*BPITCH)
#define GEMM_SMEM ((2*ASZ + 2*BSZ) * 2)

template<int OMODE>
__global__ __launch_bounds__(128, 2) void gemm_f16(
    const __half* __restrict__ A, const __half* __restrict__ B,
    const float* __restrict__ bias,
    float* __restrict__ C, __half* __restrict__ Cf,
    int M, int N, int K)
{
    extern __shared__ char smem[];
    __half* sA = (__half*)smem;
    __half* sB = sA + 2 * ASZ;

    const int tid  = threadIdx.x;
    const int lane = tid & 31;
    const int warp = tid >> 5;
    const int bm   = blockIdx.y * GBM;
    const int bn   = blockIdx.x * GBN;
    const int wm   = (warp & 1) * 64;
    const int wn   = (warp >> 1) * 64;

    float acc[4][8][4];
#pragma unroll
    for (int mi = 0; mi < 4; mi++)
#pragma unroll
        for (int n = 0; n < 8; n++)
#pragma unroll
            for (int e = 0; e < 4; e++) acc[mi][n][e] = 0.f;

    auto prefetch = [&](int st, int k0) {
        const __half* a = A + (size_t)bm * K + k0;
#pragma unroll
        for (int i = 0; i < 4; i++) {
            int idx = tid + i * 128;
            int r = idx >> 2, c = (idx & 3) * 8;
            cpa16(sptr(&sA[st * ASZ + r * APITCH + c]), a + (size_t)r * K + c);
        }
        const __half* b = B + (size_t)k0 * N + bn;
#pragma unroll
        for (int i = 0; i < 4; i++) {
            int idx = tid + i * 128;
            int r = idx >> 4, c = (idx & 15) * 8;
            cpa16(sptr(&sB[st * BSZ + r * BPITCH + c]), b + (size_t)r * N + c);
        }
        asm volatile("cp.async.commit_group;");
    };

    const int NIT = K / GBK;
    prefetch(0, 0);
    for (int it = 0; it < NIT; it++) {
        if (it + 1 < NIT) {
            prefetch((it + 1) & 1, (it + 1) * GBK);
            asm volatile("cp.async.wait_group 1;");
        } else {
            asm volatile("cp.async.wait_group 0;");
        }
        __syncthreads();
        const int st = it & 1;

#pragma unroll
        for (int kk = 0; kk < GBK; kk += 16) {
            unsigned af[4][4], bf[4][4];
#pragma unroll
            for (int mi = 0; mi < 4; mi++) {
                int row = wm + mi * 16 + (lane & 15);
                int col = kk + (lane >> 4) * 8;
                ldsm4(af[mi], sptr(&sA[st * ASZ + row * APITCH + col]));
            }
#pragma unroll
            for (int nj = 0; nj < 4; nj++) {
                int row = kk + (lane & 15);
                int col = wn + nj * 16 + (lane >> 4) * 8;
                ldsm4t(bf[nj], sptr(&sB[st * BSZ + row * BPITCH + col]));
            }
#pragma unroll
            for (int mi = 0; mi < 4; mi++)
#pragma unroll
                for (int nj = 0; nj < 4; nj++)
#pragma unroll
                    for (int sub = 0; sub < 2; sub++)
                        mma16816h(acc[mi][nj * 2 + sub], af[mi], &bf[nj][sub * 2]);
        }
        __syncthreads();
    }

#pragma unroll
    for (int mi = 0; mi < 4; mi++) {
        int r0 = bm + wm + mi * 16 + (lane >> 2);
#pragma unroll
        for (int n = 0; n < 8; n++) {
            int c0 = bn + wn + n * 8 + (lane & 3) * 2;
            float2 bv = *(const float2*)(bias + c0);
            float v00 = acc[mi][n][0] + bv.x, v01 = acc[mi][n][1] + bv.y;
            float v10 = acc[mi][n][2] + bv.x, v11 = acc[mi][n][3] + bv.y;
            if (OMODE == 0) {
                *(float2*)(C + (size_t)r0 * N + c0) = make_float2(v00, v01);
                *(float2*)(C + (size_t)(r0 + 8) * N + c0) = make_float2(v10, v11);
            } else {
                *(unsigned*)(Cf + (size_t)r0 * N + c0) = packh2(v00, v01);
                *(unsigned*)(Cf + (size_t)(r0 + 8) * N + c0) = packh2(v10, v11);
            }
        }
    }
}

// ---------------------------------------------------------------------------
// Tensor-core causal flash attention, single fp16 MMA path.
// Q,K,V,P fp16; accumulation fp32; output written fp16.
// ---------------------------------------------------------------------------
#define KPH 72
#define TSZH (64*KPH)              // halves per tile
#define STGH (2*TSZH)              // K, V
#define FLASH_SMEM (2*STGH*2)      // bytes (36864)

__global__ __launch_bounds__(256, 2) void flash_attn_mma(
    const __half* __restrict__ qkv, __half* __restrict__ outf)
{
    extern __shared__ char smraw[];
    __half* sm = (__half*)smraw;

    const int tid  = threadIdx.x;
    const int lane = tid & 31;
    const int warp = tid >> 5;
    const int bh   = blockIdx.y;
    const int b    = bh >> 4;
    const int h    = bh & (NHEAD - 1);
    const int qb   = (gridDim.x - 1) - blockIdx.x;  // heavy tiles first
    const int q0   = qb * 128;
    const int wm   = warp * 16;
    const int r    = lane >> 2;
    const int cp   = (lane & 3) * 2;
    const int qrow = q0 + wm + r;

    // ---- Q fragments straight from global (packed half2 = one u32) ----
    unsigned qf[4][4];
    {
        const size_t base  = ((size_t)(b * SEQ) + qrow) * QKV_N + h * HDIM;
        const size_t base8 = base + (size_t)8 * QKV_N;
#pragma unroll
        for (int kk = 0; kk < 4; kk++) {
            int c0 = kk * 16 + cp;
            qf[kk][0] = *(const unsigned*)(qkv + base  + c0);
            qf[kk][1] = *(const unsigned*)(qkv + base8 + c0);
            qf[kk][2] = *(const unsigned*)(qkv + base  + c0 + 8);
            qf[kk][3] = *(const unsigned*)(qkv + base8 + c0 + 8);
        }
    }

    float m0 = -1e30f, m1 = -1e30f, l0 = 0.f, l1 = 0.f;
    float o[8][4];
#pragma unroll
    for (int nf = 0; nf < 8; nf++)
#pragma unroll
        for (int e = 0; e < 4; e++) o[nf][e] = 0.f;

    const size_t koff = (size_t)EMBD + h * HDIM;
    const size_t voff = (size_t)(2 * EMBD) + h * HDIM;

    auto prefetch = [&](int st, int k0) {
#pragma unroll
        for (int i = 0; i < 4; i++) {
            int id = tid + i * 256;           // 0..1023
            int t  = id >> 9;                 // 0:K 1:V
            int rr = (id >> 3) & 63;
            int cc = (id & 7) * 8;
            const __half* src = qkv + ((size_t)(b * SEQ) + k0 + rr) * QKV_N
                              + (t ? voff : koff) + cc;
            cpa16(sptr(&sm[st * STGH + t * TSZH + rr * KPH + cc]), src);
        }
        asm volatile("cp.async.commit_group;");
    };

    const int ntiles = 2 * qb + 2;
    prefetch(0, 0);
    for (int t = 0; t < ntiles; t++) {
        const int k0 = t * 64;
        if (t + 1 < ntiles) {
            prefetch((t + 1) & 1, (t + 1) * 64);
            asm volatile("cp.async.wait_group 1;");
        } else {
            asm volatile("cp.async.wait_group 0;");
        }
        __syncthreads();
        const int st = t & 1;

        if (k0 <= q0 + wm + 15) {   // causal warp-level skip
            const __half* Kf = sm + st * STGH;
            const __half* Vf = sm + st * STGH + TSZH;

            // ---- S = Q K^T ----
            float s[8][4];
#pragma unroll
            for (int nf = 0; nf < 8; nf++)
#pragma unroll
                for (int e = 0; e < 4; e++) s[nf][e] = 0.f;

#pragma unroll
            for (int kk = 0; kk < 4; kk++) {
#pragma unroll
                for (int g = 0; g < 4; g++) {
                    unsigned kf4[4];
                    int off = (16 * g + (lane & 15)) * KPH + kk * 16 + (lane >> 4) * 8;
                    ldsm4(kf4, sptr(Kf + off));
                    unsigned b0[2] = {kf4[0], kf4[2]}, b1[2] = {kf4[1], kf4[3]};
                    mma16816h(s[2*g],     qf[kk], b0);
                    mma16816h(s[2*g + 1], qf[kk], b1);
                }
            }

            // ---- masking + online softmax ----
            const bool need_mask = (k0 + 63) > (q0 + wm);
            float mx0 = -1e30f, mx1 = -1e30f;
#pragma unroll
            for (int nf = 0; nf < 8; nf++) {
#pragma unroll
                for (int e = 0; e < 4; e++) s[nf][e] *= 0.125f;
                if (need_mask) {
                    int c0 = k0 + nf * 8 + cp;
                    if (c0     > qrow)     s[nf][0] = -1e30f;
                    if (c0 + 1 > qrow)     s[nf][1] = -1e30f;
                    if (c0     > qrow + 8) s[nf][2] = -1e30f;
                    if (c0 + 1 > qrow + 8) s[nf][3] = -1e30f;
                }
                mx0 = fmaxf(mx0, fmaxf(s[nf][0], s[nf][1]));
                mx1 = fmaxf(mx1, fmaxf(s[nf][2], s[nf][3]));
            }
            mx0 = fmaxf(mx0, __shfl_xor_sync(0xffffffffu, mx0, 1));
            mx0 = fmaxf(mx0, __shfl_xor_sync(0xffffffffu, mx0, 2));
            mx1 = fmaxf(mx1, __shfl_xor_sync(0xffffffffu, mx1, 1));
            mx1 = fmaxf(mx1, __shfl_xor_sync(0xffffffffu, mx1, 2));

            const float nm0 = fmaxf(m0, mx0), nm1 = fmaxf(m1, mx1);
            const float cr0 = __expf(m0 - nm0), cr1 = __expf(m1 - nm1);
            m0 = nm0; m1 = nm1;
            l0 *= cr0; l1 *= cr1;
#pragma unroll
            for (int nf = 0; nf < 8; nf++) {
                o[nf][0] *= cr0; o[nf][1] *= cr0;
                o[nf][2] *= cr1; o[nf][3] *= cr1;
            }

            unsigned pf[8][2];
#pragma unroll
            for (int nf = 0; nf < 8; nf++) {
                float p0 = __expf(s[nf][0] - m0);
                float p1 = __expf(s[nf][1] - m0);
                float p2 = __expf(s[nf][2] - m1);
                float p3 = __expf(s[nf][3] - m1);
                l0 += p0 + p1;
                l1 += p2 + p3;
                pf[nf][0] = packh2(p0, p1);
                pf[nf][1] = packh2(p2, p3);
            }

            // ---- O += P V ----
#pragma unroll
            for (int kp = 0; kp < 4; kp++) {
                unsigned pa[4] = {pf[2*kp][0], pf[2*kp][1], pf[2*kp+1][0], pf[2*kp+1][1]};
#pragma unroll
                for (int dg = 0; dg < 4; dg++) {
                    unsigned vf4[4];
                    int off = (kp * 16 + (lane & 15)) * KPH + dg * 16 + (lane >> 4) * 8;
                    ldsm4t(vf4, sptr(Vf + off));
                    mma16816h(o[2*dg],     pa, &vf4[0]);
                    mma16816h(o[2*dg + 1], pa, &vf4[2]);
                }
            }
        }
        __syncthreads();
    }

    // ---- finalize: quad-reduce l, normalize, store fp16 ----
    l0 += __shfl_xor_sync(0xffffffffu, l0, 1);
    l0 += __shfl_xor_sync(0xffffffffu, l0, 2);
    l1 += __shfl_xor_sync(0xffffffffu, l1, 1);
    l1 += __shfl_xor_sync(0xffffffffu, l1, 2);
    const float inv0 = 1.f / l0, inv1 = 1.f / l1;

    const size_t obase  = ((size_t)(b * SEQ) + qrow) * EMBD + h * HDIM;
    const size_t obase8 = obase + (size_t)8 * EMBD;
#pragma unroll
    for (int nf = 0; nf < 8; nf++) {
        int c0 = nf * 8 + cp;
        *(unsigned*)(outf + obase  + c0) = packh2(o[nf][0] * inv0, o[nf][1] * inv0);
        *(unsigned*)(outf + obase8 + c0) = packh2(o[nf][2] * inv1, o[nf][3] * inv1);
    }
}

// ---------------------------------------------------------------------------
// Launch
// ---------------------------------------------------------------------------
extern "C" void kernel_launch(void* const* d_in, const int* in_sizes, int n_in,
                              void* d_out, int out_size)
{
    const float* x     = (const float*)d_in[0];
    const float* W_qkv = (const float*)d_in[1];
    const float* b_qkv = (const float*)d_in[2];
    const float* W_out = (const float*)d_in[3];
    const float* b_out = (const float*)d_in[4];
    float* out = (float*)d_out;

    __half *xf, *wqf, *wof, *qkvf, *af;
    cudaGetSymbolAddress((void**)&xf,   g_xf);
    cudaGetSymbolAddress((void**)&wqf,  g_wqf);
    cudaGetSymbolAddress((void**)&wof,  g_wof);
    cudaGetSymbolAddress((void**)&qkvf, g_qkvf);
    cudaGetSymbolAddress((void**)&af,   g_af);

    const int M = BATCH * SEQ;                       // 8192

    cudaFuncSetAttribute(gemm_f16<0>, cudaFuncAttributeMaxDynamicSharedMemorySize, GEMM_SMEM);
    cudaFuncSetAttribute(gemm_f16<2>, cudaFuncAttributeMaxDynamicSharedMemorySize, GEMM_SMEM);
    cudaFuncSetAttribute(flash_attn_mma, cudaFuncAttributeMaxDynamicSharedMemorySize, FLASH_SMEM);

    // 1) convert inputs to fp16
    {
        int n4 = M * EMBD / 4;
        tofp16x4<<<(n4 + 255) / 256, 256>>>((const float4*)x, (uint2*)xf, n4);
        n4 = EMBD * QKV_N / 4;
        tofp16x4<<<(n4 + 255) / 256, 256>>>((const float4*)W_qkv, (uint2*)wqf, n4);
        n4 = EMBD * EMBD / 4;
        tofp16x4<<<(n4 + 255) / 256, 256>>>((const float4*)W_out, (uint2*)wof, n4);
    }
    // 2) QKV projection (fp16, fp32 accumulate) -> fp16 qkv
    {
        dim3 grid(QKV_N / GBN, M / GBM);
        gemm_f16<2><<<grid, 128, GEMM_SMEM>>>(xf, wqf, b_qkv, nullptr, qkvf, M, QKV_N, EMBD);
    }
    // 3) Flash attention (fp16 MMA) -> fp16 attn output
    {
        dim3 grid(SEQ / 128, BATCH * NHEAD);
        flash_attn_mma<<<grid, 256, FLASH_SMEM>>>(qkvf, af);
    }
    // 4) Output projection (fp16, fp32 accumulate) -> fp32 result
    {
        dim3 grid(EMBD / GBN, M / GBM);
        gemm_f16<0><<<grid, 128, GEMM_SMEM>>>(af, wof, b_out, out, nullptr, M, EMBD, EMBD);
    }
}